// round 13
// baseline (speedup 1.0000x reference)
#include <cuda_runtime.h>
#include <cuda_bf16.h>
#include <cstdint>

// Problem constants (fixed by the reference)
#define N_COLS  22
#define N_PAIRS 231
#define EMB     12
#define DVEC    64
#define N_PRIM  5
#define COMBO2  (EMB * EMB * 2)   // 288 floats per pair in the LUT
#define NCHUNK  8                 // pair-dimension split for kernel 2
#define CHUNKSZ ((N_PAIRS + NCHUNK - 1) / NCHUNK)   // 29
#define BT      64                // batch rows per k2 block
#define K2_THREADS 512

// Pair index table, computed on host, passed by value (constant bank)
struct PairTab { uchar2 ij[N_PAIRS]; };

// Scratch: precomputed per-pair lookup table T[p][fi][fj][o]  (266 KB)
__device__ __align__(16) float g_T[N_PAIRS * COMBO2];

// ---------------------------------------------------------------------------
// Kernel 1: warp-per-(p, fi), quarter-warp layout. No SMEM, no __syncthreads.
// Lane q=lane>>3 (quarter), ql=lane&7 holds dims 8ql..8ql+7 (two float4).
// Quarter q computes fj = 4t+q for t=0..2; 3-level shuffle reduce (xor 4,2,1).
// Also zero-initializes out[] (poisoned by harness) for kernel 2's atomics.
// ---------------------------------------------------------------------------
__global__ __launch_bounds__(256)
void build_lut_kernel(const float* __restrict__ tables,
                      const float* __restrict__ Wsmall,
                      const float* __restrict__ Wconcat,
                      const float* __restrict__ aw,
                      float* __restrict__ out, int outN,
                      const PairTab tab)
{
    // zero the output buffer
    {
        const int gz = blockIdx.x * 256 + threadIdx.x;
        if (gz < outN) out[gz] = 0.0f;
    }

    const int gwarp = (blockIdx.x * 256 + threadIdx.x) >> 5;
    if (gwarp >= N_PAIRS * EMB) return;

    const int p    = gwarp / EMB;
    const int fi   = gwarp % EMB;
    const int lane = threadIdx.x & 31;
    const int q    = lane >> 3;          // quarter 0..3
    const int ql   = lane & 7;           // dim-octet within quarter

    const int i = tab.ij[p].x;
    const int j = tab.ij[p].y;

    // primitive via one ballot (arch_weights is exact one-hot 0/1)
    const bool hot = (lane < N_PRIM) && (__ldg(&aw[p * N_PRIM + lane]) > 0.5f);
    const int  k   = __ffs(__ballot_sync(0xffffffffu, hot)) - 1;

    const float4* __restrict__ t4 = (const float4*)tables;
    const float4 PiA = __ldg(&t4[(i * EMB + fi) * 16 + 2 * ql]);
    const float4 PiB = __ldg(&t4[(i * EMB + fi) * 16 + 2 * ql + 1]);

    float4 w0A, w0B, w1A, w1B;           // Q-side weights, o = 0 / 1
    float  pp0 = 0.0f, pp1 = 0.0f;       // reduced P-part for concat
    if (k == 4) {
        const float4* __restrict__ wc = (const float4*)(Wconcat + p * 2 * (2 * DVEC));
        const float4 a0A = __ldg(&wc[2 * ql]),      a0B = __ldg(&wc[2 * ql + 1]);      // o=0 P
        const float4 a1A = __ldg(&wc[32 + 2 * ql]), a1B = __ldg(&wc[33 + 2 * ql]);     // o=1 P
        w0A = __ldg(&wc[16 + 2 * ql]);  w0B = __ldg(&wc[17 + 2 * ql]);                 // o=0 Q
        w1A = __ldg(&wc[48 + 2 * ql]);  w1B = __ldg(&wc[49 + 2 * ql]);                 // o=1 Q
        pp0 = a0A.x * PiA.x + a0A.y * PiA.y + a0A.z * PiA.z + a0A.w * PiA.w
            + a0B.x * PiB.x + a0B.y * PiB.y + a0B.z * PiB.z + a0B.w * PiB.w;
        pp1 = a1A.x * PiA.x + a1A.y * PiA.y + a1A.z * PiA.z + a1A.w * PiA.w
            + a1B.x * PiB.x + a1B.y * PiB.y + a1B.z * PiB.z + a1B.w * PiB.w;
#pragma unroll
        for (int off = 4; off; off >>= 1) {
            pp0 += __shfl_xor_sync(0xffffffffu, pp0, off);
            pp1 += __shfl_xor_sync(0xffffffffu, pp1, off);
        }
    } else {
        const float4* __restrict__ ws = (const float4*)(Wsmall + (p * 4 + k) * 2 * DVEC);
        w0A = __ldg(&ws[2 * ql]);       w0B = __ldg(&ws[2 * ql + 1]);
        w1A = __ldg(&ws[16 + 2 * ql]);  w1B = __ldg(&ws[17 + 2 * ql]);
    }

    float2* __restrict__ T2 = (float2*)g_T;

#pragma unroll
    for (int t = 0; t < 3; ++t) {
        const int fj = t * 4 + q;
        const float4 QA = __ldg(&t4[(j * EMB + fj) * 16 + 2 * ql]);
        const float4 QB = __ldg(&t4[(j * EMB + fj) * 16 + 2 * ql + 1]);

        float4 zA, zB;
        if (k == 0)      { zA.x = PiA.x + QA.x; zA.y = PiA.y + QA.y; zA.z = PiA.z + QA.z; zA.w = PiA.w + QA.w;
                           zB.x = PiB.x + QB.x; zB.y = PiB.y + QB.y; zB.z = PiB.z + QB.z; zB.w = PiB.w + QB.w; }
        else if (k == 1) { zA.x = PiA.x * QA.x; zA.y = PiA.y * QA.y; zA.z = PiA.z * QA.z; zA.w = PiA.w * QA.w;
                           zB.x = PiB.x * QB.x; zB.y = PiB.y * QB.y; zB.z = PiB.z * QB.z; zB.w = PiB.w * QB.w; }
        else if (k == 2) { zA.x = fmaxf(PiA.x, QA.x); zA.y = fmaxf(PiA.y, QA.y); zA.z = fmaxf(PiA.z, QA.z); zA.w = fmaxf(PiA.w, QA.w);
                           zB.x = fmaxf(PiB.x, QB.x); zB.y = fmaxf(PiB.y, QB.y); zB.z = fmaxf(PiB.z, QB.z); zB.w = fmaxf(PiB.w, QB.w); }
        else if (k == 3) { zA.x = fminf(PiA.x, QA.x); zA.y = fminf(PiA.y, QA.y); zA.z = fminf(PiA.z, QA.z); zA.w = fminf(PiA.w, QA.w);
                           zB.x = fminf(PiB.x, QB.x); zB.y = fminf(PiB.y, QB.y); zB.z = fminf(PiB.z, QB.z); zB.w = fminf(PiB.w, QB.w); }
        else             { zA = QA; zB = QB; }   // concat: Q-part only

        float s0 = zA.x * w0A.x + zA.y * w0A.y + zA.z * w0A.z + zA.w * w0A.w
                 + zB.x * w0B.x + zB.y * w0B.y + zB.z * w0B.z + zB.w * w0B.w;
        float s1 = zA.x * w1A.x + zA.y * w1A.y + zA.z * w1A.z + zA.w * w1A.w
                 + zB.x * w1B.x + zB.y * w1B.y + zB.z * w1B.z + zB.w * w1B.w;
#pragma unroll
        for (int off = 4; off; off >>= 1) {
            s0 += __shfl_xor_sync(0xffffffffu, s0, off);
            s1 += __shfl_xor_sync(0xffffffffu, s1, off);
        }
        if (k == 4) { s0 += pp0; s1 += pp1; }

        if (ql == 0)
            T2[p * (EMB * EMB) + fi * EMB + fj] = make_float2(s0, s1);
    }
}

// ---------------------------------------------------------------------------
// Kernel 2: out[b, :] += sum_{p in chunk} T[p, f[i_p], f[j_p], :]
// grid = (NCHUNK, B/64), 512 threads: 16 warps = 2 row-subtiles x 8 stripes.
// Chunk-major grid keeps the L1 chunk-affinity (stride 148 mod 8 = 4 ->
// each SM hosts only chunks {c, c+4}; 2 x 33 KB of g_T fits L1).
// Per-block staging/reduction overhead amortized over 64 rows (2x R12).
// lane = batch row; warp stripe strides the chunk's 29 pairs (<=4 unrolled
// independent gathers, all 32 lanes inside one pair's 1.15 KB region).
// Warps 0/1 fold the 8 stripes per row-group, then atomicAdd.
// ---------------------------------------------------------------------------
__global__ __launch_bounds__(K2_THREADS)
void accumulate_kernel(const int* __restrict__ feats,
                       float* __restrict__ out,
                       int B,
                       const PairTab tab)
{
    __shared__ int    shf[BT][N_COLS + 1];   // stride 23: coprime with 32 banks
    __shared__ float2 shred[16][32];

    const int tid    = threadIdx.x;
    const int lane   = tid & 31;
    const int warp   = tid >> 5;             // 0..15
    const int subrow = warp & 1;             // row-subtile (rows 0-31 / 32-63)
    const int stripe = warp >> 1;            // pair stripe 0..7
    const int bbase  = blockIdx.y * BT;      // tile
    const int p0     = blockIdx.x * CHUNKSZ; // chunk
    const int npair  = min(N_PAIRS - p0, CHUNKSZ);

    // coalesced, cooperative load of this block's 64 feats rows
    for (int e = tid; e < BT * N_COLS; e += K2_THREADS) {
        const int row = e / N_COLS, col = e - row * N_COLS;
        const int b   = bbase + row;
        shf[row][col] = (b < B) ? feats[b * N_COLS + col] : 0;
    }
    __syncthreads();

    const int brow = subrow * 32 + lane;     // 0..63
    const float2* __restrict__ T2 = (const float2*)g_T;
    float ax = 0.0f, ay = 0.0f;

    // stripe s handles chunk-local pairs s, s+8, ... (<= 4 independent gathers)
#pragma unroll 4
    for (int t = stripe; t < npair; t += 8) {
        const uchar2 ij = tab.ij[p0 + t];        // constant bank, uniform
        const int fi = shf[brow][ij.x];
        const int fj = shf[brow][ij.y];
        const float2 v = __ldg(&T2[(p0 + t) * (EMB * EMB) + fi * EMB + fj]);
        ax += v.x;
        ay += v.y;
    }

    shred[warp][lane] = make_float2(ax, ay);
    __syncthreads();

    // warp g (0/1) folds the 8 stripes of row-group g
    if (warp < 2) {
        float sx = 0.0f, sy = 0.0f;
#pragma unroll
        for (int s = 0; s < 8; ++s) {
            const float2 v = shred[2 * s + warp][lane];
            sx += v.x;
            sy += v.y;
        }
        const int b = bbase + warp * 32 + lane;
        if (b < B) {
            atomicAdd(&out[b * 2 + 0], sx);
            atomicAdd(&out[b * 2 + 1], sy);
        }
    }
}

// ---------------------------------------------------------------------------
// Launch: two kernels, single stream (proven fastest structure), graph-safe.
// Inputs (metadata order): feats(i32), tables(f32), W_small(f32),
//                          W_concat(f32), arch_weights(f32)
// ---------------------------------------------------------------------------
extern "C" void kernel_launch(void* const* d_in, const int* in_sizes, int n_in,
                              void* d_out, int out_size)
{
    const int*   feats   = (const int*)  d_in[0];
    const float* tables  = (const float*)d_in[1];
    const float* Wsmall  = (const float*)d_in[2];
    const float* Wconcat = (const float*)d_in[3];
    const float* aw      = (const float*)d_in[4];
    float*       out     = (float*)d_out;

    const int B = in_sizes[0] / N_COLS;   // 4096

    // host-side triu(N_COLS, 1) pair table -> constant-bank kernel param
    PairTab tab;
    {
        int p = 0;
        for (int i = 0; i < N_COLS; ++i)
            for (int j = i + 1; j < N_COLS; ++j, ++p)
                tab.ij[p] = make_uchar2((unsigned char)i, (unsigned char)j);
    }

    const int k1_blocks = (N_PAIRS * EMB * 32 + 255) / 256;   // 347
    build_lut_kernel<<<k1_blocks, 256>>>(tables, Wsmall, Wconcat, aw,
                                         out, out_size, tab);

    dim3 grid(NCHUNK, (B + BT - 1) / BT); // 8 x 64 = 512 blocks, chunk-major
    accumulate_kernel<<<grid, K2_THREADS>>>(feats, out, B, tab);
}